// round 1
// baseline (speedup 1.0000x reference)
#include <cuda_runtime.h>
#include <math_constants.h>

// Problem shape (fixed by the reference): B=4, S=2048, D=1024, H=16, Dh=64.
#define DM 1024
#define NH 16
#define DH 64
#define BB 4
#define SS 2048
#define MM (BB*SS)   // 8192 rows

// Scratch (allocation-free rule: __device__ globals). 4 x 32 MiB.
__device__ float g_Q[(size_t)MM * DM];
__device__ float g_K[(size_t)MM * DM];
__device__ float g_V[(size_t)MM * DM];
__device__ float g_Ao[(size_t)MM * DM];

// ---------------------------------------------------------------------------
// GEMM: Y[m,n] = sum_k A[m,k] * W[n,k]   (Linear: x @ W^T, W stored [out,in])
// M=8192, N=1024, K=1024. Tile 128x64, BK=16, 256 threads, 8x4 per thread.
// ---------------------------------------------------------------------------
#define BM 128
#define BN 64
#define BK 16

__global__ __launch_bounds__(256) void gemm_xwt(const float* __restrict__ A,
                                                const float* __restrict__ W,
                                                float* __restrict__ Y) {
    __shared__ float As[BK][BM + 4];
    __shared__ float Bs[BK][BN + 4];

    const int tid = threadIdx.x;
    const int tx = tid & 15;        // 0..15 -> 4 cols each
    const int ty = tid >> 4;        // 0..15 -> 8 rows each
    const int m0 = blockIdx.y * BM;
    const int n0 = blockIdx.x * BN;

    const int la_m = tid >> 2;          // 0..63
    const int la_k = (tid & 3) << 2;    // 0,4,8,12

    float acc[8][4];
#pragma unroll
    for (int i = 0; i < 8; i++)
#pragma unroll
        for (int j = 0; j < 4; j++) acc[i][j] = 0.f;

    for (int k0 = 0; k0 < DM; k0 += BK) {
        float4 a0 = *(const float4*)(A + (size_t)(m0 + la_m)      * DM + k0 + la_k);
        float4 a1 = *(const float4*)(A + (size_t)(m0 + la_m + 64) * DM + k0 + la_k);
        float4 b0 = *(const float4*)(W + (size_t)(n0 + la_m)      * DM + k0 + la_k);

        As[la_k + 0][la_m] = a0.x; As[la_k + 1][la_m] = a0.y;
        As[la_k + 2][la_m] = a0.z; As[la_k + 3][la_m] = a0.w;
        As[la_k + 0][la_m + 64] = a1.x; As[la_k + 1][la_m + 64] = a1.y;
        As[la_k + 2][la_m + 64] = a1.z; As[la_k + 3][la_m + 64] = a1.w;
        Bs[la_k + 0][la_m] = b0.x; Bs[la_k + 1][la_m] = b0.y;
        Bs[la_k + 2][la_m] = b0.z; Bs[la_k + 3][la_m] = b0.w;
        __syncthreads();

#pragma unroll
        for (int kk = 0; kk < BK; kk++) {
            float4 a04 = *(const float4*)&As[kk][ty * 8];
            float4 a14 = *(const float4*)&As[kk][ty * 8 + 4];
            float4 b4  = *(const float4*)&Bs[kk][tx * 4];
            float av[8] = {a04.x, a04.y, a04.z, a04.w, a14.x, a14.y, a14.z, a14.w};
            float bv[4] = {b4.x, b4.y, b4.z, b4.w};
#pragma unroll
            for (int i = 0; i < 8; i++)
#pragma unroll
                for (int j = 0; j < 4; j++)
                    acc[i][j] += av[i] * bv[j];
        }
        __syncthreads();
    }

#pragma unroll
    for (int i = 0; i < 8; i++) {
        float4 v = make_float4(acc[i][0], acc[i][1], acc[i][2], acc[i][3]);
        *(float4*)(Y + (size_t)(m0 + ty * 8 + i) * DM + n0 + tx * 4) = v;
    }
}

// ---------------------------------------------------------------------------
// Causal attention, flash-style. Q/K/V live in [B,S,H*Dh] layout (natural
// GEMM output). One block = 64 q-rows of one (b,h); one thread = one q-row
// (full row ownership -> softmax entirely thread-local). K/V tiles (64x64)
// staged in shared; score dot reads are warp-broadcast LDS.
// Streaming online softmax: rescale on new max (expected ~ln(S) times/row).
// ---------------------------------------------------------------------------
__global__ __launch_bounds__(64) void attn_kernel(const float* __restrict__ Q,
                                                  const float* __restrict__ K,
                                                  const float* __restrict__ V,
                                                  float* __restrict__ O) {
    __shared__ float4 Ks[64 * 16];
    __shared__ float4 Vs[64 * 16];

    const int r  = threadIdx.x;      // q-row within tile
    const int qt = blockIdx.x;       // q tile index
    const int h  = blockIdx.y;
    const int b  = blockIdx.z;
    const int qi = qt * 64 + r;
    const size_t qrow = ((size_t)(b * SS + qi)) * DM + h * DH;

    float4 q4[16], acc4[16];
    const float4* qg = (const float4*)(Q + qrow);
#pragma unroll
    for (int i = 0; i < 16; i++) {
        float4 v = qg[i];
        q4[i]   = make_float4(v.x * 0.125f, v.y * 0.125f, v.z * 0.125f, v.w * 0.125f);
        acc4[i] = make_float4(0.f, 0.f, 0.f, 0.f);
    }
    float mval = -CUDART_INF_F;
    float lval = 0.f;

    for (int t = 0; t <= qt; t++) {
        // Cooperative load of K,V tile: 1024 float4s over 64 threads, coalesced.
#pragma unroll
        for (int i = 0; i < 16; i++) {
            int fl  = i * 64 + r;
            int row = fl >> 4;
            int c4  = fl & 15;
            size_t g = ((size_t)(b * SS + t * 64 + row)) * DM + h * DH + c4 * 4;
            Ks[row * 16 + c4] = *(const float4*)(K + g);
            Vs[row * 16 + c4] = *(const float4*)(V + g);
        }
        __syncthreads();

        const int cmax = (t == qt) ? (r + 1) : 64;   // causal mask
        for (int c = 0; c < cmax; c++) {
            const float4* kr = &Ks[c * 16];
            float s0 = 0.f, s1 = 0.f, s2 = 0.f, s3 = 0.f;
#pragma unroll
            for (int i = 0; i < 16; i += 4) {
                float4 k0 = kr[i], k1 = kr[i + 1], k2 = kr[i + 2], k3 = kr[i + 3];
                s0 += q4[i].x   * k0.x + q4[i].y   * k0.y + q4[i].z   * k0.z + q4[i].w   * k0.w;
                s1 += q4[i+1].x * k1.x + q4[i+1].y * k1.y + q4[i+1].z * k1.z + q4[i+1].w * k1.w;
                s2 += q4[i+2].x * k2.x + q4[i+2].y * k2.y + q4[i+2].z * k2.z + q4[i+2].w * k2.w;
                s3 += q4[i+3].x * k3.x + q4[i+3].y * k3.y + q4[i+3].z * k3.z + q4[i+3].w * k3.w;
            }
            float s = (s0 + s1) + (s2 + s3);

            if (s > mval) {
                float corr = __expf(mval - s);   // exp(-inf)=0 on first hit: zeroes l/acc
                lval *= corr;
#pragma unroll
                for (int i = 0; i < 16; i++) {
                    acc4[i].x *= corr; acc4[i].y *= corr;
                    acc4[i].z *= corr; acc4[i].w *= corr;
                }
                mval = s;
            }
            float p = __expf(s - mval);
            lval += p;

            const float4* vr = &Vs[c * 16];
#pragma unroll
            for (int i = 0; i < 16; i++) {
                float4 vv = vr[i];
                acc4[i].x += p * vv.x; acc4[i].y += p * vv.y;
                acc4[i].z += p * vv.z; acc4[i].w += p * vv.w;
            }
        }
        __syncthreads();
    }

    const float inv = 1.0f / lval;
    float4* og = (float4*)(O + qrow);
#pragma unroll
    for (int i = 0; i < 16; i++)
        og[i] = make_float4(acc4[i].x * inv, acc4[i].y * inv,
                            acc4[i].z * inv, acc4[i].w * inv);
}

// ---------------------------------------------------------------------------
// Launch: 3 projection GEMMs -> attention -> output GEMM. All default-stream
// kernel launches; no sync, no alloc -> graph-capturable.
// ---------------------------------------------------------------------------
extern "C" void kernel_launch(void* const* d_in, const int* in_sizes, int n_in,
                              void* d_out, int out_size) {
    const float* X  = (const float*)d_in[0];
    const float* WQ = (const float*)d_in[1];
    const float* WK = (const float*)d_in[2];
    const float* WV = (const float*)d_in[3];
    const float* WO = (const float*)d_in[4];
    float* out = (float*)d_out;

    void *pq, *pk, *pv, *po;
    cudaGetSymbolAddress(&pq, g_Q);
    cudaGetSymbolAddress(&pk, g_K);
    cudaGetSymbolAddress(&pv, g_V);
    cudaGetSymbolAddress(&po, g_Ao);

    dim3 gg(DM / BN, MM / BM);           // (16, 64)
    gemm_xwt<<<gg, 256>>>(X, WQ, (float*)pq);
    gemm_xwt<<<gg, 256>>>(X, WK, (float*)pk);
    gemm_xwt<<<gg, 256>>>(X, WV, (float*)pv);

    dim3 ga(SS / 64, NH, BB);            // (32, 16, 4)
    attn_kernel<<<ga, 64>>>((const float*)pq, (const float*)pk,
                            (const float*)pv, (float*)po);

    gemm_xwt<<<gg, 256>>>((const float*)po, WO, out);
}

// round 4
// speedup vs baseline: 1.0863x; 1.0863x over previous
#include <cuda_runtime.h>
#include <cuda_bf16.h>
#include <math_constants.h>
#include <cstdint>

// Shape (fixed): B=4, S=2048, D=1024, H=16, Dh=64.
#define DM 1024
#define NH 16
#define DH 64
#define BB 4
#define SS 2048
#define MM (BB*SS)        // 8192
#define KTOT 3072         // 3-term split: K' = 3*DM

// ---------------------------------------------------------------------------
// Scratch (__device__ globals; no allocs allowed). ~248 MB total.
// ---------------------------------------------------------------------------
__device__ float g_Q [(size_t)MM * DM];
__device__ float g_K [(size_t)MM * DM];
__device__ float g_V [(size_t)MM * DM];
__device__ float g_Ao[(size_t)MM * DM];
__device__ __nv_bfloat16 g_Xc [(size_t)MM * KTOT];   // [Ah | Ah | Al]
__device__ __nv_bfloat16 g_Aoc[(size_t)MM * KTOT];
__device__ __nv_bfloat16 g_Wc [4][(size_t)DM * KTOT]; // [Wh | Wl | Wh]

__device__ __forceinline__ uint32_t smem_u32(const void* p) {
    uint32_t a;
    asm("{ .reg .u64 t; cvta.to.shared.u64 t, %1; cvt.u32.u64 %0, t; }"
        : "=r"(a) : "l"(p));
    return a;
}

// ---------------------------------------------------------------------------
// fp32 -> bf16 hi/lo, written into 3 K-segments of a [rows x 3072] buffer.
// A-side: h at k, h at k+1024, l at k+2048  -> (off2=1024, offL=2048)
// B-side: h at k, l at k+1024, h at k+2048  -> (off2=2048, offL=1024)
// ---------------------------------------------------------------------------
__global__ __launch_bounds__(256) void conv_split(const float* __restrict__ x,
                                                  __nv_bfloat16* __restrict__ o,
                                                  int n, int off2, int offL) {
    int i = (blockIdx.x * 256 + threadIdx.x) * 4;
    if (i >= n) return;
    float4 v = *(const float4*)(x + i);
    __nv_bfloat16 h0 = __float2bfloat16_rn(v.x);
    __nv_bfloat16 h1 = __float2bfloat16_rn(v.y);
    __nv_bfloat16 h2 = __float2bfloat16_rn(v.z);
    __nv_bfloat16 h3 = __float2bfloat16_rn(v.w);
    __nv_bfloat16 l0 = __float2bfloat16_rn(v.x - __bfloat162float(h0));
    __nv_bfloat16 l1 = __float2bfloat16_rn(v.y - __bfloat162float(h1));
    __nv_bfloat16 l2 = __float2bfloat16_rn(v.z - __bfloat162float(h2));
    __nv_bfloat16 l3 = __float2bfloat16_rn(v.w - __bfloat162float(h3));
    int m = i >> 10;             // row (DM=1024 cols in)
    int k = i & 1023;
    __nv_bfloat16* r = o + (size_t)m * KTOT + k;
    __nv_bfloat162 hA(h0, h1), hB(h2, h3), lA(l0, l1), lB(l2, l3);
    *(__nv_bfloat162*)(r)            = hA; *(__nv_bfloat162*)(r + 2)        = hB;
    *(__nv_bfloat162*)(r + off2)     = hA; *(__nv_bfloat162*)(r + off2 + 2) = hB;
    *(__nv_bfloat162*)(r + offL)     = lA; *(__nv_bfloat162*)(r + offL + 2) = lB;
}

// ---------------------------------------------------------------------------
// bf16 GEMM via mma.sync.m16n8k16 (sm_80 path; compiles under compute_103).
// Y[m,n] = sum_k A[m,k]*B[n,k],  M=8192, N=1024, K=3072, fp32 accumulate.
// CTA 128x128, BK=32, 4-stage cp.async pipeline, 8 warps of 64x32.
// smem swizzle: 16B chunk (row,kc) -> row*64 + ((kc ^ ((row>>1)&3))<<4)
//   -> conflict-free for both cp.async stores and ldmatrix.x4 reads.
// ---------------------------------------------------------------------------
#define STAGE_BYTES 16384     // A 8KB + B 8KB
#define BSM_OFF 8192
#define NKIT (KTOT/32)        // 96

#define SWCHUNK(row, kc) ((row)*64 + (((kc) ^ (((row)>>1)&3)) << 4))

__device__ __forceinline__ void g_load_stage(uint32_t sbase, int st, int it,
                                             const char* Ag, const char* Bg,
                                             int tid) {
    uint32_t sb = sbase + st * STAGE_BYTES;
    size_t koff = (size_t)it * 64;          // 32 bf16 = 64B along k
#pragma unroll
    for (int j = 0; j < 2; j++) {
        int id = j * 256 + tid;
        int row = id >> 2, kc = id & 3;
        uint32_t d = sb + SWCHUNK(row, kc);
        const char* s = Ag + (size_t)row * (KTOT * 2) + koff + kc * 16;
        asm volatile("cp.async.cg.shared.global [%0], [%1], 16;" :: "r"(d), "l"(s));
    }
#pragma unroll
    for (int j = 0; j < 2; j++) {
        int id = j * 256 + tid;
        int row = id >> 2, kc = id & 3;
        uint32_t d = sb + BSM_OFF + SWCHUNK(row, kc);
        const char* s = Bg + (size_t)row * (KTOT * 2) + koff + kc * 16;
        asm volatile("cp.async.cg.shared.global [%0], [%1], 16;" :: "r"(d), "l"(s));
    }
    asm volatile("cp.async.commit_group;" ::: "memory");
}

__global__ __launch_bounds__(256) void gemm_mma(const __nv_bfloat16* __restrict__ A,
                                                const __nv_bfloat16* __restrict__ B,
                                                float* __restrict__ Y) {
    extern __shared__ char sm[];
    const uint32_t sbase = smem_u32(sm);
    const int tid = threadIdx.x;
    const int lane = tid & 31;
    const int wid = tid >> 5;
    const int warp_m = wid & 1;      // 2 warp-rows
    const int warp_n = wid >> 1;     // 4 warp-cols
    const int m0 = blockIdx.y * 128;
    const int n0 = blockIdx.x * 128;

    const char* Ag = (const char*)A + (size_t)m0 * (KTOT * 2);
    const char* Bg = (const char*)B + (size_t)n0 * (KTOT * 2);

    const int q = lane >> 3, r = lane & 7;

    float c[4][4][4];
#pragma unroll
    for (int mi = 0; mi < 4; mi++)
#pragma unroll
        for (int ni = 0; ni < 4; ni++)
#pragma unroll
            for (int e = 0; e < 4; e++) c[mi][ni][e] = 0.f;

    g_load_stage(sbase, 0, 0, Ag, Bg, tid);
    g_load_stage(sbase, 1, 1, Ag, Bg, tid);
    g_load_stage(sbase, 2, 2, Ag, Bg, tid);

#pragma unroll 1
    for (int i = 0; i < NKIT; i++) {
        asm volatile("cp.async.wait_group 2;" ::: "memory");
        __syncthreads();

        if (i + 3 < NKIT) g_load_stage(sbase, (i + 3) & 3, i + 3, Ag, Bg, tid);
        else asm volatile("cp.async.commit_group;" ::: "memory");

        const uint32_t sb = sbase + (i & 3) * STAGE_BYTES;
#pragma unroll
        for (int ks = 0; ks < 2; ks++) {
            const int kc0 = ks * 2;
            uint32_t a[4][4], b[2][4];
#pragma unroll
            for (int mi = 0; mi < 4; mi++) {
                int row = warp_m * 64 + mi * 16 + ((q & 1) << 3) + r;
                int kc = kc0 + (q >> 1);
                uint32_t ad = sb + SWCHUNK(row, kc);
                asm volatile("ldmatrix.sync.aligned.m8n8.x4.shared.b16 "
                             "{%0,%1,%2,%3}, [%4];"
                             : "=r"(a[mi][0]), "=r"(a[mi][1]),
                               "=r"(a[mi][2]), "=r"(a[mi][3]) : "r"(ad));
            }
#pragma unroll
            for (int pi = 0; pi < 2; pi++) {
                int row = warp_n * 32 + pi * 16 + ((q >> 1) << 3) + r;
                int kc = kc0 + (q & 1);
                uint32_t bd = sb + BSM_OFF + SWCHUNK(row, kc);
                asm volatile("ldmatrix.sync.aligned.m8n8.x4.shared.b16 "
                             "{%0,%1,%2,%3}, [%4];"
                             : "=r"(b[pi][0]), "=r"(b[pi][1]),
                               "=r"(b[pi][2]), "=r"(b[pi][3]) : "r"(bd));
            }
#pragma unroll
            for (int mi = 0; mi < 4; mi++)
#pragma unroll
                for (int ni = 0; ni < 4; ni++) {
                    uint32_t b0 = b[ni >> 1][2 * (ni & 1)];
                    uint32_t b1 = b[ni >> 1][2 * (ni & 1) + 1];
                    asm volatile(
                        "mma.sync.aligned.m16n8k16.row.col.f32.bf16.bf16.f32 "
                        "{%0,%1,%2,%3}, {%4,%5,%6,%7}, {%8,%9}, {%0,%1,%2,%3};"
                        : "+f"(c[mi][ni][0]), "+f"(c[mi][ni][1]),
                          "+f"(c[mi][ni][2]), "+f"(c[mi][ni][3])
                        : "r"(a[mi][0]), "r"(a[mi][1]),
                          "r"(a[mi][2]), "r"(a[mi][3]),
                          "r"(b0), "r"(b1));
                }
        }
    }

    // Epilogue: direct register -> gmem (float2 per 16x8 tile half).
    const int mrow = (lane >> 2);
    const int ncol = 2 * (lane & 3);
#pragma unroll
    for (int mi = 0; mi < 4; mi++) {
        int mr = m0 + warp_m * 64 + mi * 16 + mrow;
#pragma unroll
        for (int ni = 0; ni < 4; ni++) {
            int nc = n0 + warp_n * 32 + ni * 8 + ncol;
            *(float2*)(Y + (size_t)mr * DM + nc)       = make_float2(c[mi][ni][0], c[mi][ni][1]);
            *(float2*)(Y + (size_t)(mr + 8) * DM + nc) = make_float2(c[mi][ni][2], c[mi][ni][3]);
        }
    }
}

// ---------------------------------------------------------------------------
// Causal flash attention, fp32. Thread pair owns one q-row (32 elems each).
// ---------------------------------------------------------------------------
__global__ __launch_bounds__(128) void attn_kernel(const float* __restrict__ Q,
                                                   const float* __restrict__ K,
                                                   const float* __restrict__ V,
                                                   float* __restrict__ O) {
    __shared__ float4 Ks[64 * 16];
    __shared__ float4 Vs[64 * 16];

    const int tid = threadIdx.x;
    const int p   = tid >> 1;
    const int hf  = tid & 1;
    const int qt  = blockIdx.x;
    const int h   = blockIdx.y;
    const int b   = blockIdx.z;
    const int qi  = qt * 64 + p;
    const size_t qrow = ((size_t)(b * SS + qi)) * DM + h * DH + hf * 32;
    const unsigned pmask = 3u << ((tid & 31) & ~1);

    float4 q4[8], acc4[8];
    const float4* qg = (const float4*)(Q + qrow);
#pragma unroll
    for (int i = 0; i < 8; i++) {
        float4 v = qg[i];
        q4[i]   = make_float4(v.x * 0.125f, v.y * 0.125f, v.z * 0.125f, v.w * 0.125f);
        acc4[i] = make_float4(0.f, 0.f, 0.f, 0.f);
    }
    float mval = -CUDART_INF_F;
    float lval = 0.f;

    for (int t = 0; t <= qt; t++) {
#pragma unroll
        for (int i = 0; i < 8; i++) {
            int fl  = i * 128 + tid;
            int row = fl >> 4, c4 = fl & 15;
            size_t g = ((size_t)(b * SS + t * 64 + row)) * DM + h * DH + c4 * 4;
            Ks[row * 16 + c4] = *(const float4*)(K + g);
            Vs[row * 16 + c4] = *(const float4*)(V + g);
        }
        __syncthreads();

        const int cmax = (t == qt) ? (p + 1) : 64;
        for (int c = 0; c < cmax; c++) {
            const float4* kr = &Ks[c * 16 + hf * 8];
            float s0 = 0.f, s1 = 0.f;
#pragma unroll
            for (int i = 0; i < 8; i += 2) {
                float4 k0 = kr[i], k1 = kr[i + 1];
                s0 += q4[i].x   * k0.x + q4[i].y   * k0.y + q4[i].z   * k0.z + q4[i].w   * k0.w;
                s1 += q4[i+1].x * k1.x + q4[i+1].y * k1.y + q4[i+1].z * k1.z + q4[i+1].w * k1.w;
            }
            float part = s0 + s1;
            float s = part + __shfl_xor_sync(pmask, part, 1);

            if (s > mval) {
                float corr = __expf(mval - s);
                lval *= corr;
#pragma unroll
                for (int i = 0; i < 8; i++) {
                    acc4[i].x *= corr; acc4[i].y *= corr;
                    acc4[i].z *= corr; acc4[i].w *= corr;
                }
                mval = s;
            }
            float pc = __expf(s - mval);
            lval += pc;

            const float4* vr = &Vs[c * 16 + hf * 8];
#pragma unroll
            for (int i = 0; i < 8; i++) {
                float4 vv = vr[i];
                acc4[i].x += pc * vv.x; acc4[i].y += pc * vv.y;
                acc4[i].z += pc * vv.z; acc4[i].w += pc * vv.w;
            }
        }
        __syncthreads();
    }

    const float inv = 1.0f / lval;
    float4* og = (float4*)(O + qrow);
#pragma unroll
    for (int i = 0; i < 8; i++)
        og[i] = make_float4(acc4[i].x * inv, acc4[i].y * inv,
                            acc4[i].z * inv, acc4[i].w * inv);
}

// ---------------------------------------------------------------------------
// Launch.
// ---------------------------------------------------------------------------
extern "C" void kernel_launch(void* const* d_in, const int* in_sizes, int n_in,
                              void* d_out, int out_size) {
    const float* X  = (const float*)d_in[0];
    const float* W[4] = { (const float*)d_in[1], (const float*)d_in[2],
                          (const float*)d_in[3], (const float*)d_in[4] };
    float* out = (float*)d_out;

    void *pq, *pk, *pv, *po, *pxc, *paoc, *pwc;
    cudaGetSymbolAddress(&pq,  g_Q);   cudaGetSymbolAddress(&pk,  g_K);
    cudaGetSymbolAddress(&pv,  g_V);   cudaGetSymbolAddress(&po,  g_Ao);
    cudaGetSymbolAddress(&pxc, g_Xc);  cudaGetSymbolAddress(&paoc, g_Aoc);
    cudaGetSymbolAddress(&pwc, g_Wc);

    __nv_bfloat16* Xc  = (__nv_bfloat16*)pxc;
    __nv_bfloat16* Aoc = (__nv_bfloat16*)paoc;
    __nv_bfloat16* Wc  = (__nv_bfloat16*)pwc;

    cudaFuncSetAttribute(gemm_mma, cudaFuncAttributeMaxDynamicSharedMemorySize,
                         4 * STAGE_BYTES);

    const int nX = MM * DM;
    const int nW = DM * DM;
    const size_t wstep = (size_t)DM * KTOT;

    // A-side: [h,h,l]; B-side: [h,l,h]
    conv_split<<<nX / 1024, 256>>>(X, Xc, nX, 1024, 2048);
    for (int w = 0; w < 4; w++)
        conv_split<<<nW / 1024, 256>>>(W[w], Wc + w * wstep, nW, 2048, 1024);

    dim3 gg(DM / 128, MM / 128);   // (8, 64)
    gemm_mma<<<gg, 256, 4 * STAGE_BYTES>>>(Xc, Wc + 0 * wstep, (float*)pq);
    gemm_mma<<<gg, 256, 4 * STAGE_BYTES>>>(Xc, Wc + 1 * wstep, (float*)pk);
    gemm_mma<<<gg, 256, 4 * STAGE_BYTES>>>(Xc, Wc + 2 * wstep, (float*)pv);

    dim3 ga(SS / 64, NH, BB);      // (32, 16, 4)
    attn_kernel<<<ga, 128>>>((const float*)pq, (const float*)pk,
                             (const float*)pv, (float*)po);

    conv_split<<<nX / 1024, 256>>>((const float*)po, Aoc, nX, 1024, 2048);
    gemm_mma<<<gg, 256, 4 * STAGE_BYTES>>>(Aoc, Wc + 3 * wstep, out);
}